// round 1
// baseline (speedup 1.0000x reference)
#include <cuda_runtime.h>
#include <math.h>

// Problem constants
#define BB   4
#define TT   4096
#define HH   8
#define LDIM 128
#define FFND 512
#define DD   1024
#define TOK  (BB*TT)          // 16384 tokens
#define TED  2048

// Scratch (device-global arrays: allowed; cudaMalloc is not)
__device__ float g_ss[BB * 2 * DD];                       // scale/shift (B, 2D)
__device__ float g_h1[(long)TOK * HH * FFND];             // gelu(x@W1+b1)  (t,h,f) 256MB
__device__ float g_y [(long)TOK * DD];                    // per-head MLP out, concat
__device__ float g_g [(long)TOK * DD];                    // silu(modulated LN(y))

__device__ __forceinline__ float silu_f(float v) { return v / (1.0f + expf(-v)); }
__device__ __forceinline__ float gelu_f(float v) { return 0.5f * v * (1.0f + erff(v * 0.70710678118654752f)); }

// ---------------------------------------------------------------------------
// Kernel 1: ss[b, :] = silu(emb[b,:]) @ emb_W + emb_b      (4 x 2048)
// grid (8, 4), 256 threads: block loads silu(emb[b]) to smem, each thread one j.
// ---------------------------------------------------------------------------
__global__ __launch_bounds__(256) void emb_kernel(
    const float* __restrict__ emb, const float* __restrict__ embW,
    const float* __restrict__ embb, float* __restrict__ ss)
{
    __shared__ float se[TED];
    const int b = blockIdx.y;
    const int j = blockIdx.x * 256 + threadIdx.x;
    for (int i = threadIdx.x; i < TED; i += 256) {
        float e = emb[b * TED + i];
        se[i] = silu_f(e);
    }
    __syncthreads();
    float acc = embb[j];
    #pragma unroll 8
    for (int k = 0; k < TED; k++)
        acc += se[k] * embW[(long)k * TED + j];
    ss[b * TED + j] = acc;
}

// ---------------------------------------------------------------------------
// Generic batched SGEMM, 128x128 block tile, BK=8, 256 threads, 8x8 per thread.
// C[z] = epi( A[z] @ B[z] + bias[z] )   — all dims divide tiles exactly.
// EPI: 0 = bias+gelu (MLP1), 1 = bias (MLP2), 2 = bias + residual(extra) (out).
// ---------------------------------------------------------------------------
template <int EPI>
__global__ __launch_bounds__(256) void sgemm_epi(
    const float* __restrict__ A, const float* __restrict__ B,
    float* __restrict__ C, const float* __restrict__ bias,
    const float* __restrict__ extra,
    int lda, int ldb, int ldc, int K,
    long aB, long bB, long cB, int biasB)
{
    __shared__ float As[8][132];   // padded: conflict-light, 16B-aligned rows
    __shared__ float Bs[8][128];

    const int tid = threadIdx.x;
    const int tx = tid & 15;       // 16 col groups
    const int ty = tid >> 4;       // 16 row groups

    const float* Ap = A + aB * blockIdx.z
                    + (long)(blockIdx.y * 128 + (tid >> 1)) * lda + (tid & 1) * 4;
    const float* Bp = B + bB * blockIdx.z
                    + (long)(tid >> 5) * ldb + blockIdx.x * 128 + (tid & 31) * 4;

    float acc[8][8];
    #pragma unroll
    for (int i = 0; i < 8; i++)
        #pragma unroll
        for (int j = 0; j < 8; j++) acc[i][j] = 0.0f;

    for (int k0 = 0; k0 < K; k0 += 8) {
        float4 av = *(const float4*)(Ap + k0);
        float4 bv = *(const float4*)(Bp + (long)k0 * ldb);
        const int ak = (tid & 1) * 4, ar = tid >> 1;
        As[ak + 0][ar] = av.x; As[ak + 1][ar] = av.y;
        As[ak + 2][ar] = av.z; As[ak + 3][ar] = av.w;
        *(float4*)&Bs[tid >> 5][(tid & 31) * 4] = bv;
        __syncthreads();

        #pragma unroll
        for (int kk = 0; kk < 8; kk++) {
            float a[8], b[8];
            *(float4*)&a[0] = *(const float4*)&As[kk][ty * 8];
            *(float4*)&a[4] = *(const float4*)&As[kk][ty * 8 + 4];
            *(float4*)&b[0] = *(const float4*)&Bs[kk][tx * 8];
            *(float4*)&b[4] = *(const float4*)&Bs[kk][tx * 8 + 4];
            #pragma unroll
            for (int i = 0; i < 8; i++)
                #pragma unroll
                for (int j = 0; j < 8; j++)
                    acc[i][j] += a[i] * b[j];
        }
        __syncthreads();
    }

    const int n0 = blockIdx.x * 128 + tx * 8;
    const int m0 = blockIdx.y * 128 + ty * 8;
    const long cz = cB * blockIdx.z;
    #pragma unroll
    for (int i = 0; i < 8; i++) {
        const int  m  = m0 + i;
        const long co = cz + (long)m * ldc + n0;
        float out[8];
        #pragma unroll
        for (int j = 0; j < 8; j++) {
            float v = acc[i][j] + bias[biasB * blockIdx.z + n0 + j];
            if (EPI == 0) v = gelu_f(v);
            if (EPI == 2) v += extra[(long)m * ldc + n0 + j];
            out[j] = v;
        }
        *(float4*)(C + co)     = *(float4*)&out[0];
        *(float4*)(C + co + 4) = *(float4*)&out[4];
    }
}

// ---------------------------------------------------------------------------
// Kernel 4: per-token LayerNorm -> modulate (scale/shift) -> SiLU.
// One block (256 thr) per token; 4 floats/thread covers D=1024.
// ---------------------------------------------------------------------------
__global__ __launch_bounds__(256) void ln_mod_silu(
    const float* __restrict__ y, const float* __restrict__ ss,
    const float* __restrict__ lnw, const float* __restrict__ lnb,
    float* __restrict__ g)
{
    const long t = blockIdx.x;
    const int tid = threadIdx.x;
    const int c = tid * 4;

    float4 v = *(const float4*)(y + t * DD + c);
    float s = v.x + v.y + v.z + v.w;
    float q = v.x * v.x + v.y * v.y + v.z * v.z + v.w * v.w;
    #pragma unroll
    for (int o = 16; o; o >>= 1) {
        s += __shfl_xor_sync(0xffffffffu, s, o);
        q += __shfl_xor_sync(0xffffffffu, q, o);
    }
    __shared__ float rs[8], rq[8];
    __shared__ float smean, srstd;
    if ((tid & 31) == 0) { rs[tid >> 5] = s; rq[tid >> 5] = q; }
    __syncthreads();
    if (tid == 0) {
        float S = 0.f, Q = 0.f;
        #pragma unroll
        for (int i = 0; i < 8; i++) { S += rs[i]; Q += rq[i]; }
        float mean = S * (1.0f / DD);
        float var  = Q * (1.0f / DD) - mean * mean;
        smean = mean;
        srstd = rsqrtf(var + 1e-5f);
    }
    __syncthreads();
    const float mean = smean, rstd = srstd;

    const int b = (int)(t >> 12);   // 4096 tokens per batch
    float4 sc = *(const float4*)(ss + b * TED + c);
    float4 sh = *(const float4*)(ss + b * TED + DD + c);
    float4 w4 = *(const float4*)(lnw + c);
    float4 b4 = *(const float4*)(lnb + c);

    float4 o;
    float h;
    h = (v.x - mean) * rstd * w4.x + b4.x; h = h * (1.f + sc.x) + sh.x; o.x = silu_f(h);
    h = (v.y - mean) * rstd * w4.y + b4.y; h = h * (1.f + sc.y) + sh.y; o.y = silu_f(h);
    h = (v.z - mean) * rstd * w4.z + b4.z; h = h * (1.f + sc.z) + sh.z; o.z = silu_f(h);
    h = (v.w - mean) * rstd * w4.w + b4.w; h = h * (1.f + sc.w) + sh.w; o.w = silu_f(h);
    *(float4*)(g + t * DD + c) = o;
}

// ---------------------------------------------------------------------------
extern "C" void kernel_launch(void* const* d_in, const int* in_sizes, int n_in,
                              void* d_out, int out_size)
{
    const float* x     = (const float*)d_in[0];   // (4,4096,1024)
    const float* emb   = (const float*)d_in[1];   // (4,2048)
    const float* W1    = (const float*)d_in[2];   // (8,128,512)
    const float* b1    = (const float*)d_in[3];   // (8,512)
    const float* W2    = (const float*)d_in[4];   // (8,512,128)
    const float* b2    = (const float*)d_in[5];   // (8,128)
    const float* ln_w  = (const float*)d_in[6];   // (1024)
    const float* ln_b  = (const float*)d_in[7];   // (1024)
    const float* emb_W = (const float*)d_in[8];   // (2048,2048)
    const float* emb_b = (const float*)d_in[9];   // (2048)
    const float* out_W = (const float*)d_in[10];  // (1024,1024)
    const float* out_b = (const float*)d_in[11];  // (1024)
    float* out = (float*)d_out;

    float *ss, *h1, *yv, *gg;
    cudaGetSymbolAddress((void**)&ss, g_ss);
    cudaGetSymbolAddress((void**)&h1, g_h1);
    cudaGetSymbolAddress((void**)&yv, g_y);
    cudaGetSymbolAddress((void**)&gg, g_g);

    // 1) scale/shift from emb
    emb_kernel<<<dim3(8, 4), 256>>>(emb, emb_W, emb_b, ss);

    // 2) h1 = gelu(xh @ W1 + b1)   per head: M=16384, N=512, K=128
    sgemm_epi<0><<<dim3(4, 128, 8), 256>>>(
        x, W1, h1, b1, nullptr,
        /*lda*/DD, /*ldb*/FFND, /*ldc*/HH * FFND, /*K*/LDIM,
        /*aB*/LDIM, /*bB*/(long)LDIM * FFND, /*cB*/FFND, /*biasB*/FFND);

    // 3) y = h1 @ W2 + b2          per head: M=16384, N=128, K=512
    sgemm_epi<1><<<dim3(1, 128, 8), 256>>>(
        h1, W2, yv, b2, nullptr,
        /*lda*/HH * FFND, /*ldb*/LDIM, /*ldc*/DD, /*K*/FFND,
        /*aB*/FFND, /*bB*/(long)FFND * LDIM, /*cB*/LDIM, /*biasB*/LDIM);

    // 4) g = silu( LN(y)*ln_w+ln_b times (1+scale) + shift )
    ln_mod_silu<<<TOK, 256>>>(yv, ss, ln_w, ln_b, gg);

    // 5) out = x + g @ out_W + out_b    M=16384, N=1024, K=1024
    sgemm_epi<2><<<dim3(8, 128, 1), 256>>>(
        gg, out_W, out, out_b, x,
        /*lda*/DD, /*ldb*/DD, /*ldc*/DD, /*K*/DD,
        0, 0, 0, 0);
}

// round 3
// speedup vs baseline: 2.0230x; 2.0230x over previous
#include <cuda_runtime.h>
#include <cstdint>
#include <math.h>

// Problem constants
#define BB   4
#define TT   4096
#define HH   8
#define LDIM 128
#define FFND 512
#define DD   1024
#define TOK  (BB*TT)
#define TED  2048

// GEMM tiling
#define BM 128
#define BN 128
#define BKC 32
#define ASTRIDE 36     // padded: conflict-free for frag loads (4*gid+tig covers 32 banks)
#define BSTRIDE 136    // padded: 8*tig+gid covers 32 banks
#define SMEM_FLOATS (2*(BM*ASTRIDE + BKC*BSTRIDE))
#define SMEM_BYTES  (SMEM_FLOATS*4)

// Scratch
__device__ float g_ss[BB * 2 * DD];
__device__ float g_h1[(long)TOK * HH * FFND];
__device__ float g_y [(long)TOK * DD];
__device__ float g_g [(long)TOK * DD];

__device__ __forceinline__ float silu_f(float v) { return v / (1.0f + expf(-v)); }
__device__ __forceinline__ float gelu_f(float v) { return 0.5f * v * (1.0f + erff(v * 0.70710678118654752f)); }
__device__ __forceinline__ uint32_t f2tf32(float f) {
    uint32_t u;
    asm("cvt.rna.tf32.f32 %0, %1;" : "=r"(u) : "f"(f));
    return u;
}

// ---------------------------------------------------------------------------
// tf32 mma.sync GEMM: C[z] = epi( A[z] @ B[z] + bias[z] )
//   A: rows at (A + aZ*z + row*lda), K contiguous
//   B: [K, N] row-major at (B + bZ*z), ldb
// Block: 128x128, BK=32 double-buffered. 8 warps = 2(m) x 4(n), warp 64x32.
// Each warp: 4 m-tiles (16) x 4 n-tiles (8), k in 4 steps of 8.
// EPI: 0 = bias+gelu, 1 = bias, 2 = bias+residual(extra)
// ---------------------------------------------------------------------------
template <int EPI>
__global__ void __launch_bounds__(256, 1) mma_gemm(
    const float* __restrict__ A, long aZ, int lda,
    const float* __restrict__ B, long bZ, int ldb,
    float* __restrict__ C, long cZ, int ldc,
    const float* __restrict__ bias, int biasZ,
    const float* __restrict__ extra, int K)
{
    extern __shared__ float sm[];
    float* As = sm;                          // [2][BM][ASTRIDE]
    float* Bs = sm + 2 * BM * ASTRIDE;       // [2][BKC][BSTRIDE]

    const int tid  = threadIdx.x;
    const int lane = tid & 31, wid = tid >> 5;
    const int wm   = wid >> 2, wn = wid & 3;       // 2 x 4 warp grid
    const int gid  = lane >> 2, tig = lane & 3;
    const int bx = blockIdx.x, by = blockIdx.y, bz = blockIdx.z;
    const int nC = K / BKC;

    const float* Ap = A + aZ * bz + (long)(by * BM) * lda;
    const float* Bp = B + bZ * bz + bx * BN;

    // global load mapping
    const int ar = tid >> 1;                 // A row 0..127
    const int ac = (tid & 1) * 16;           // A k-offset 0/16
    const int br = tid >> 3;                 // B k-row 0..31
    const int bc = (tid & 7) * 4;            // B n-offset, step 32 per p

    float4 pa[4], pb[4];
    float acc[4][4][4];
    #pragma unroll
    for (int i = 0; i < 4; i++)
        #pragma unroll
        for (int j = 0; j < 4; j++)
            #pragma unroll
            for (int e = 0; e < 4; e++) acc[i][j][e] = 0.0f;

    // chunk 0 load + store
    #pragma unroll
    for (int p = 0; p < 4; p++) {
        pa[p] = *(const float4*)(Ap + (long)ar * lda + ac + p * 4);
        pb[p] = *(const float4*)(Bp + (long)br * ldb + bc + p * 32);
    }
    {
        float* Ab = As;  float* Bb = Bs;
        #pragma unroll
        for (int p = 0; p < 4; p++) {
            uint4 wa = { f2tf32(pa[p].x), f2tf32(pa[p].y), f2tf32(pa[p].z), f2tf32(pa[p].w) };
            *(uint4*)(Ab + ar * ASTRIDE + ac + p * 4) = wa;
            uint4 wb = { f2tf32(pb[p].x), f2tf32(pb[p].y), f2tf32(pb[p].z), f2tf32(pb[p].w) };
            *(uint4*)(Bb + br * BSTRIDE + bc + p * 32) = wb;
        }
    }
    __syncthreads();

    for (int c = 0; c < nC; c++) {
        const int cur = c & 1;
        const bool more = (c + 1 < nC);
        if (more) {
            const int k0 = (c + 1) * BKC;
            #pragma unroll
            for (int p = 0; p < 4; p++) {
                pa[p] = *(const float4*)(Ap + (long)ar * lda + k0 + ac + p * 4);
                pb[p] = *(const float4*)(Bp + (long)(k0 + br) * ldb + bc + p * 32);
            }
        }
        // compute current buffer
        {
            const float* Ab = As + cur * BM * ASTRIDE;
            const float* Bb = Bs + cur * BKC * BSTRIDE;
            #pragma unroll
            for (int ks = 0; ks < 4; ks++) {
                const int kb = ks * 8;
                uint32_t af[4][4], bf[4][2];
                #pragma unroll
                for (int i = 0; i < 4; i++) {
                    const float* ap = Ab + (wm * 64 + i * 16 + gid) * ASTRIDE + kb + tig;
                    af[i][0] = __float_as_uint(ap[0]);
                    af[i][1] = __float_as_uint(ap[8 * ASTRIDE]);
                    af[i][2] = __float_as_uint(ap[4]);
                    af[i][3] = __float_as_uint(ap[8 * ASTRIDE + 4]);
                }
                #pragma unroll
                for (int j = 0; j < 4; j++) {
                    const float* bp = Bb + (kb + tig) * BSTRIDE + wn * 32 + j * 8 + gid;
                    bf[j][0] = __float_as_uint(bp[0]);
                    bf[j][1] = __float_as_uint(bp[4 * BSTRIDE]);
                }
                #pragma unroll
                for (int i = 0; i < 4; i++)
                    #pragma unroll
                    for (int j = 0; j < 4; j++)
                        asm volatile(
                            "mma.sync.aligned.m16n8k8.row.col.f32.tf32.tf32.f32 "
                            "{%0,%1,%2,%3}, {%4,%5,%6,%7}, {%8,%9}, {%0,%1,%2,%3};"
                            : "+f"(acc[i][j][0]), "+f"(acc[i][j][1]),
                              "+f"(acc[i][j][2]), "+f"(acc[i][j][3])
                            : "r"(af[i][0]), "r"(af[i][1]), "r"(af[i][2]), "r"(af[i][3]),
                              "r"(bf[j][0]), "r"(bf[j][1]));
            }
        }
        if (more) {
            __syncthreads();
            const int nxt = cur ^ 1;
            float* Ab = As + nxt * BM * ASTRIDE;
            float* Bb = Bs + nxt * BKC * BSTRIDE;
            #pragma unroll
            for (int p = 0; p < 4; p++) {
                uint4 wa = { f2tf32(pa[p].x), f2tf32(pa[p].y), f2tf32(pa[p].z), f2tf32(pa[p].w) };
                *(uint4*)(Ab + ar * ASTRIDE + ac + p * 4) = wa;
                uint4 wb = { f2tf32(pb[p].x), f2tf32(pb[p].y), f2tf32(pb[p].z), f2tf32(pb[p].w) };
                *(uint4*)(Bb + br * BSTRIDE + bc + p * 32) = wb;
            }
            __syncthreads();
        }
    }

    // ---- epilogue ----
    const long zC = cZ * bz;
    const float* bsp = bias + (long)biasZ * bz;
    #pragma unroll
    for (int i = 0; i < 4; i++) {
        const int r0 = by * BM + wm * 64 + i * 16 + gid;
        #pragma unroll
        for (int j = 0; j < 4; j++) {
            const int cn = bx * BN + wn * 32 + j * 8 + tig * 2;
            const float b0 = bsp[cn], b1 = bsp[cn + 1];
            float v00 = acc[i][j][0] + b0, v01 = acc[i][j][1] + b1;
            float v10 = acc[i][j][2] + b0, v11 = acc[i][j][3] + b1;
            if (EPI == 0) {
                v00 = gelu_f(v00); v01 = gelu_f(v01);
                v10 = gelu_f(v10); v11 = gelu_f(v11);
            }
            if (EPI == 2) {
                v00 += extra[(long)r0 * ldc + cn];
                v01 += extra[(long)r0 * ldc + cn + 1];
                v10 += extra[(long)(r0 + 8) * ldc + cn];
                v11 += extra[(long)(r0 + 8) * ldc + cn + 1];
            }
            float2 lo = { v00, v01 }, hi = { v10, v11 };
            *(float2*)(C + zC + (long)r0 * ldc + cn)       = lo;
            *(float2*)(C + zC + (long)(r0 + 8) * ldc + cn) = hi;
        }
    }
}

// ---------------------------------------------------------------------------
// emb: ss[b,:] = silu(emb[b,:]) @ emb_W + emb_b
// ---------------------------------------------------------------------------
__global__ __launch_bounds__(256) void emb_kernel(
    const float* __restrict__ emb, const float* __restrict__ embW,
    const float* __restrict__ embb, float* __restrict__ ss)
{
    __shared__ float se[TED];
    const int b = blockIdx.y;
    const int j = blockIdx.x * 256 + threadIdx.x;
    for (int i = threadIdx.x; i < TED; i += 256)
        se[i] = silu_f(emb[b * TED + i]);
    __syncthreads();
    float acc = embb[j];
    #pragma unroll 8
    for (int k = 0; k < TED; k++)
        acc += se[k] * embW[(long)k * TED + j];
    ss[b * TED + j] = acc;
}

// ---------------------------------------------------------------------------
// per-token LayerNorm -> modulate -> SiLU
// ---------------------------------------------------------------------------
__global__ __launch_bounds__(256) void ln_mod_silu(
    const float* __restrict__ y, const float* __restrict__ ss,
    const float* __restrict__ lnw, const float* __restrict__ lnb,
    float* __restrict__ g)
{
    const long t = blockIdx.x;
    const int tid = threadIdx.x;
    const int c = tid * 4;

    float4 v = *(const float4*)(y + t * DD + c);
    float s = v.x + v.y + v.z + v.w;
    float q = v.x * v.x + v.y * v.y + v.z * v.z + v.w * v.w;
    #pragma unroll
    for (int o = 16; o; o >>= 1) {
        s += __shfl_xor_sync(0xffffffffu, s, o);
        q += __shfl_xor_sync(0xffffffffu, q, o);
    }
    __shared__ float rs[8], rq[8];
    __shared__ float smean, srstd;
    if ((tid & 31) == 0) { rs[tid >> 5] = s; rq[tid >> 5] = q; }
    __syncthreads();
    if (tid == 0) {
        float S = 0.f, Q = 0.f;
        #pragma unroll
        for (int i = 0; i < 8; i++) { S += rs[i]; Q += rq[i]; }
        float mean = S * (1.0f / DD);
        float var  = Q * (1.0f / DD) - mean * mean;
        smean = mean;
        srstd = rsqrtf(var + 1e-5f);
    }
    __syncthreads();
    const float mean = smean, rstd = srstd;

    const int b = (int)(t >> 12);
    float4 sc = *(const float4*)(ss + b * TED + c);
    float4 sh = *(const float4*)(ss + b * TED + DD + c);
    float4 w4 = *(const float4*)(lnw + c);
    float4 b4 = *(const float4*)(lnb + c);

    float4 o; float h;
    h = (v.x - mean) * rstd * w4.x + b4.x; h = h * (1.f + sc.x) + sh.x; o.x = silu_f(h);
    h = (v.y - mean) * rstd * w4.y + b4.y; h = h * (1.f + sc.y) + sh.y; o.y = silu_f(h);
    h = (v.z - mean) * rstd * w4.z + b4.z; h = h * (1.f + sc.z) + sh.z; o.z = silu_f(h);
    h = (v.w - mean) * rstd * w4.w + b4.w; h = h * (1.f + sc.w) + sh.w; o.w = silu_f(h);
    *(float4*)(g + t * DD + c) = o;
}

// ---------------------------------------------------------------------------
extern "C" void kernel_launch(void* const* d_in, const int* in_sizes, int n_in,
                              void* d_out, int out_size)
{
    const float* x     = (const float*)d_in[0];
    const float* emb   = (const float*)d_in[1];
    const float* W1    = (const float*)d_in[2];
    const float* b1    = (const float*)d_in[3];
    const float* W2    = (const float*)d_in[4];
    const float* b2    = (const float*)d_in[5];
    const float* ln_w  = (const float*)d_in[6];
    const float* ln_b  = (const float*)d_in[7];
    const float* emb_W = (const float*)d_in[8];
    const float* emb_b = (const float*)d_in[9];
    const float* out_W = (const float*)d_in[10];
    const float* out_b = (const float*)d_in[11];
    float* out = (float*)d_out;

    float *ss, *h1, *yv, *gg;
    cudaGetSymbolAddress((void**)&ss, g_ss);
    cudaGetSymbolAddress((void**)&h1, g_h1);
    cudaGetSymbolAddress((void**)&yv, g_y);
    cudaGetSymbolAddress((void**)&gg, g_g);

    cudaFuncSetAttribute(mma_gemm<0>, cudaFuncAttributeMaxDynamicSharedMemorySize, SMEM_BYTES);
    cudaFuncSetAttribute(mma_gemm<1>, cudaFuncAttributeMaxDynamicSharedMemorySize, SMEM_BYTES);
    cudaFuncSetAttribute(mma_gemm<2>, cudaFuncAttributeMaxDynamicSharedMemorySize, SMEM_BYTES);

    // 1) scale/shift
    emb_kernel<<<dim3(8, 4), 256>>>(emb, emb_W, emb_b, ss);

    // 2) h1 = gelu(xh @ W1 + b1): per head M=16384, N=512, K=128
    mma_gemm<0><<<dim3(4, 128, 8), 256, SMEM_BYTES>>>(
        x, 128, DD,
        W1, (long)LDIM * FFND, FFND,
        h1, FFND, HH * FFND,
        b1, FFND, nullptr, LDIM);

    // 3) y = h1 @ W2 + b2: per head M=16384, N=128, K=512
    mma_gemm<1><<<dim3(1, 128, 8), 256, SMEM_BYTES>>>(
        h1, FFND, HH * FFND,
        W2, (long)FFND * LDIM, LDIM,
        yv, LDIM, DD,
        b2, LDIM, nullptr, FFND);

    // 4) g = silu(modulated LN(y))
    ln_mod_silu<<<TOK, 256>>>(yv, ss, ln_w, ln_b, gg);

    // 5) out = x + g @ out_W + out_b: M=16384, N=1024, K=1024
    mma_gemm<2><<<dim3(8, 128, 1), 256, SMEM_BYTES>>>(
        gg, 0, DD,
        out_W, 0, DD,
        out, 0, DD,
        out_b, 0, x, DD);
}

// round 4
// speedup vs baseline: 2.0977x; 1.0369x over previous
#include <cuda_runtime.h>
#include <cstdint>
#include <math.h>

// Problem constants
#define BB   4
#define TT   4096
#define HH   8
#define LDIM 128
#define FFND 512
#define DD   1024
#define TOK  (BB*TT)
#define TED  2048

// GEMM tiling
#define BM 128
#define BN 128
#define BKC 32
#define STAGES 4
#define ASTRIDE 36     // floats; row = 144B (16B-aligned), conflict-free frag LDS
#define BSTRIDE 136    // floats; row = 544B (16B-aligned), conflict-free frag LDS
#define STAGE_FLOATS (BM*ASTRIDE + BKC*BSTRIDE)
#define SMEM_BYTES  (STAGES*STAGE_FLOATS*4)

// Scratch
__device__ float g_ss[BB * 2 * DD];
__device__ float g_h1[(long)TOK * HH * FFND];
__device__ float g_y [(long)TOK * DD];
__device__ float g_g [(long)TOK * DD];
__device__ float g_xr[(long)TOK * DD];          // tf32-rounded x
__device__ float g_w1r[HH * LDIM * FFND];       // tf32-rounded W1
__device__ float g_w2r[HH * FFND * LDIM];       // tf32-rounded W2
__device__ float g_owr[DD * DD];                // tf32-rounded out_W

__device__ __forceinline__ float silu_f(float v) { return v / (1.0f + expf(-v)); }
__device__ __forceinline__ float gelu_f(float v) { return 0.5f * v * (1.0f + erff(v * 0.70710678118654752f)); }
__device__ __forceinline__ uint32_t f2tf32(float f) {
    uint32_t u;
    asm("cvt.rna.tf32.f32 %0, %1;" : "=r"(u) : "f"(f));
    return u;
}
__device__ __forceinline__ float rnd_tf32(float f) { return __uint_as_float(f2tf32(f)); }
static __device__ __forceinline__ uint32_t smem_u32(const void* p) {
    uint32_t a;
    asm("{ .reg .u64 t; cvta.to.shared.u64 t, %1; cvt.u32.u64 %0, t; }" : "=r"(a) : "l"(p));
    return a;
}
__device__ __forceinline__ void cp_async16(uint32_t dst, const void* src) {
    asm volatile("cp.async.cg.shared.global [%0], [%1], 16;" :: "r"(dst), "l"(src));
}
#define CP_COMMIT() asm volatile("cp.async.commit_group;" ::: "memory")
#define CP_WAIT2()  asm volatile("cp.async.wait_group 2;" ::: "memory")

// ---------------------------------------------------------------------------
// Pre-round: out[i] = tf32_rna(in[i]), vectorized
// ---------------------------------------------------------------------------
__global__ __launch_bounds__(256) void round_tf32_kernel(
    const float4* __restrict__ in, float4* __restrict__ out, int n4)
{
    int i = blockIdx.x * 256 + threadIdx.x;
    if (i < n4) {
        float4 v = in[i];
        v.x = rnd_tf32(v.x); v.y = rnd_tf32(v.y);
        v.z = rnd_tf32(v.z); v.w = rnd_tf32(v.w);
        out[i] = v;
    }
}

// ---------------------------------------------------------------------------
// tf32 mma.sync GEMM with cp.async 4-stage pipeline.
// Inputs MUST be pre-rounded to tf32. Block 128x128, BK=32.
// 8 warps = 2(m) x 4(n), warp tile 64x32; m16n8k8 fragments.
// EPI: 0 = bias+gelu+round (h1), 1 = bias (yv), 2 = bias+residual (out)
// ---------------------------------------------------------------------------
template <int EPI>
__global__ void __launch_bounds__(256, 1) mma_gemm(
    const float* __restrict__ A, long aZ, int lda,
    const float* __restrict__ B, long bZ, int ldb,
    float* __restrict__ C, long cZ, int ldc,
    const float* __restrict__ bias, int biasZ,
    const float* __restrict__ extra, int K)
{
    extern __shared__ float sm[];
    float* As = sm;                               // [STAGES][BM][ASTRIDE]
    float* Bs = sm + STAGES * BM * ASTRIDE;       // [STAGES][BKC][BSTRIDE]
    const uint32_t sA = smem_u32(As);
    const uint32_t sB = smem_u32(Bs);

    const int tid  = threadIdx.x;
    const int lane = tid & 31, wid = tid >> 5;
    const int wm   = wid >> 2, wn = wid & 3;
    const int gid  = lane >> 2, tig = lane & 3;
    const int bx = blockIdx.x, by = blockIdx.y, bz = blockIdx.z;
    const int nC = K / BKC;

    const float* Ap = A + aZ * bz + (long)(by * BM) * lda;
    const float* Bp = B + bZ * bz + bx * BN;

    // cp.async loader mapping (per thread: 4 chunks A + 4 chunks B, 16B each)
    const int ar = tid >> 1, ag = (tid & 1) * 4;   // A: row, 16B-group base
    const int bk = tid >> 3, bg = tid & 7;         // B: k-row, 16B-group base

    float acc[4][4][4];
    #pragma unroll
    for (int i = 0; i < 4; i++)
        #pragma unroll
        for (int j = 0; j < 4; j++)
            #pragma unroll
            for (int e = 0; e < 4; e++) acc[i][j][e] = 0.0f;

    auto issue = [&](int c, int s) {
        const float* a_src = Ap + (long)ar * lda + c * BKC;
        const uint32_t a_dst = sA + (uint32_t)(s * BM * ASTRIDE + ar * ASTRIDE) * 4;
        #pragma unroll
        for (int p = 0; p < 4; p++) {
            const int g = ag + p;
            cp_async16(a_dst + g * 16, a_src + g * 4);
        }
        const float* b_src = Bp + (long)(c * BKC + bk) * ldb;
        const uint32_t b_dst = sB + (uint32_t)(s * BKC * BSTRIDE + bk * BSTRIDE) * 4;
        #pragma unroll
        for (int p = 0; p < 4; p++) {
            const int g = bg + p * 8;
            cp_async16(b_dst + g * 16, b_src + g * 4);
        }
    };

    // prologue: stages 0..STAGES-2
    #pragma unroll
    for (int s = 0; s < STAGES - 1; s++) {
        if (s < nC) issue(s, s);
        CP_COMMIT();
    }

    for (int c = 0; c < nC; c++) {
        CP_WAIT2();
        __syncthreads();
        const int nxt = c + STAGES - 1;
        if (nxt < nC) issue(nxt, nxt & (STAGES - 1));
        CP_COMMIT();

        const float* Ab = As + (c & (STAGES - 1)) * BM * ASTRIDE;
        const float* Bb = Bs + (c & (STAGES - 1)) * BKC * BSTRIDE;
        #pragma unroll
        for (int ks = 0; ks < 4; ks++) {
            const int kb = ks * 8;
            uint32_t af[4][4], bf[4][2];
            #pragma unroll
            for (int i = 0; i < 4; i++) {
                const float* ap = Ab + (wm * 64 + i * 16 + gid) * ASTRIDE + kb + tig;
                af[i][0] = __float_as_uint(ap[0]);
                af[i][1] = __float_as_uint(ap[8 * ASTRIDE]);
                af[i][2] = __float_as_uint(ap[4]);
                af[i][3] = __float_as_uint(ap[8 * ASTRIDE + 4]);
            }
            #pragma unroll
            for (int j = 0; j < 4; j++) {
                const float* bp = Bb + (kb + tig) * BSTRIDE + wn * 32 + j * 8 + gid;
                bf[j][0] = __float_as_uint(bp[0]);
                bf[j][1] = __float_as_uint(bp[4 * BSTRIDE]);
            }
            #pragma unroll
            for (int i = 0; i < 4; i++)
                #pragma unroll
                for (int j = 0; j < 4; j++)
                    asm volatile(
                        "mma.sync.aligned.m16n8k8.row.col.f32.tf32.tf32.f32 "
                        "{%0,%1,%2,%3}, {%4,%5,%6,%7}, {%8,%9}, {%0,%1,%2,%3};"
                        : "+f"(acc[i][j][0]), "+f"(acc[i][j][1]),
                          "+f"(acc[i][j][2]), "+f"(acc[i][j][3])
                        : "r"(af[i][0]), "r"(af[i][1]), "r"(af[i][2]), "r"(af[i][3]),
                          "r"(bf[j][0]), "r"(bf[j][1]));
        }
    }

    // ---- epilogue ----
    const long zC = cZ * bz;
    const float* bsp = bias + (long)biasZ * bz;
    #pragma unroll
    for (int i = 0; i < 4; i++) {
        const int r0 = by * BM + wm * 64 + i * 16 + gid;
        #pragma unroll
        for (int j = 0; j < 4; j++) {
            const int cn = bx * BN + wn * 32 + j * 8 + tig * 2;
            const float b0 = bsp[cn], b1 = bsp[cn + 1];
            float v00 = acc[i][j][0] + b0, v01 = acc[i][j][1] + b1;
            float v10 = acc[i][j][2] + b0, v11 = acc[i][j][3] + b1;
            if (EPI == 0) {
                v00 = rnd_tf32(gelu_f(v00)); v01 = rnd_tf32(gelu_f(v01));
                v10 = rnd_tf32(gelu_f(v10)); v11 = rnd_tf32(gelu_f(v11));
            }
            if (EPI == 2) {
                v00 += extra[(long)r0 * ldc + cn];
                v01 += extra[(long)r0 * ldc + cn + 1];
                v10 += extra[(long)(r0 + 8) * ldc + cn];
                v11 += extra[(long)(r0 + 8) * ldc + cn + 1];
            }
            float2 lo = { v00, v01 }, hi = { v10, v11 };
            *(float2*)(C + zC + (long)r0 * ldc + cn)       = lo;
            *(float2*)(C + zC + (long)(r0 + 8) * ldc + cn) = hi;
        }
    }
}

// ---------------------------------------------------------------------------
// emb: ss[b,:] = silu(emb[b,:]) @ emb_W + emb_b
// ---------------------------------------------------------------------------
__global__ __launch_bounds__(256) void emb_kernel(
    const float* __restrict__ emb, const float* __restrict__ embW,
    const float* __restrict__ embb, float* __restrict__ ss)
{
    __shared__ float se[TED];
    const int b = blockIdx.y;
    const int j = blockIdx.x * 256 + threadIdx.x;
    for (int i = threadIdx.x; i < TED; i += 256)
        se[i] = silu_f(emb[b * TED + i]);
    __syncthreads();
    float acc = embb[j];
    #pragma unroll 8
    for (int k = 0; k < TED; k++)
        acc += se[k] * embW[(long)k * TED + j];
    ss[b * TED + j] = acc;
}

// ---------------------------------------------------------------------------
// per-token LayerNorm -> modulate -> SiLU -> tf32 round (feeds GEMM3)
// ---------------------------------------------------------------------------
__global__ __launch_bounds__(256) void ln_mod_silu(
    const float* __restrict__ y, const float* __restrict__ ss,
    const float* __restrict__ lnw, const float* __restrict__ lnb,
    float* __restrict__ g)
{
    const long t = blockIdx.x;
    const int tid = threadIdx.x;
    const int c = tid * 4;

    float4 v = *(const float4*)(y + t * DD + c);
    float s = v.x + v.y + v.z + v.w;
    float q = v.x * v.x + v.y * v.y + v.z * v.z + v.w * v.w;
    #pragma unroll
    for (int o = 16; o; o >>= 1) {
        s += __shfl_xor_sync(0xffffffffu, s, o);
        q += __shfl_xor_sync(0xffffffffu, q, o);
    }
    __shared__ float rs[8], rq[8];
    __shared__ float smean, srstd;
    if ((tid & 31) == 0) { rs[tid >> 5] = s; rq[tid >> 5] = q; }
    __syncthreads();
    if (tid == 0) {
        float S = 0.f, Q = 0.f;
        #pragma unroll
        for (int i = 0; i < 8; i++) { S += rs[i]; Q += rq[i]; }
        float mean = S * (1.0f / DD);
        float var  = Q * (1.0f / DD) - mean * mean;
        smean = mean;
        srstd = rsqrtf(var + 1e-5f);
    }
    __syncthreads();
    const float mean = smean, rstd = srstd;

    const int b = (int)(t >> 12);
    float4 sc = *(const float4*)(ss + b * TED + c);
    float4 sh = *(const float4*)(ss + b * TED + DD + c);
    float4 w4 = *(const float4*)(lnw + c);
    float4 b4 = *(const float4*)(lnb + c);

    float4 o; float h;
    h = (v.x - mean) * rstd * w4.x + b4.x; h = h * (1.f + sc.x) + sh.x; o.x = rnd_tf32(silu_f(h));
    h = (v.y - mean) * rstd * w4.y + b4.y; h = h * (1.f + sc.y) + sh.y; o.y = rnd_tf32(silu_f(h));
    h = (v.z - mean) * rstd * w4.z + b4.z; h = h * (1.f + sc.z) + sh.z; o.z = rnd_tf32(silu_f(h));
    h = (v.w - mean) * rstd * w4.w + b4.w; h = h * (1.f + sc.w) + sh.w; o.w = rnd_tf32(silu_f(h));
    *(float4*)(g + t * DD + c) = o;
}

// ---------------------------------------------------------------------------
extern "C" void kernel_launch(void* const* d_in, const int* in_sizes, int n_in,
                              void* d_out, int out_size)
{
    const float* x     = (const float*)d_in[0];
    const float* emb   = (const float*)d_in[1];
    const float* W1    = (const float*)d_in[2];
    const float* b1    = (const float*)d_in[3];
    const float* W2    = (const float*)d_in[4];
    const float* b2    = (const float*)d_in[5];
    const float* ln_w  = (const float*)d_in[6];
    const float* ln_b  = (const float*)d_in[7];
    const float* emb_W = (const float*)d_in[8];
    const float* emb_b = (const float*)d_in[9];
    const float* out_W = (const float*)d_in[10];
    const float* out_b = (const float*)d_in[11];
    float* out = (float*)d_out;

    float *ss, *h1, *yv, *gg, *xr, *w1r, *w2r, *owr;
    cudaGetSymbolAddress((void**)&ss, g_ss);
    cudaGetSymbolAddress((void**)&h1, g_h1);
    cudaGetSymbolAddress((void**)&yv, g_y);
    cudaGetSymbolAddress((void**)&gg, g_g);
    cudaGetSymbolAddress((void**)&xr, g_xr);
    cudaGetSymbolAddress((void**)&w1r, g_w1r);
    cudaGetSymbolAddress((void**)&w2r, g_w2r);
    cudaGetSymbolAddress((void**)&owr, g_owr);

    cudaFuncSetAttribute(mma_gemm<0>, cudaFuncAttributeMaxDynamicSharedMemorySize, SMEM_BYTES);
    cudaFuncSetAttribute(mma_gemm<1>, cudaFuncAttributeMaxDynamicSharedMemorySize, SMEM_BYTES);
    cudaFuncSetAttribute(mma_gemm<2>, cudaFuncAttributeMaxDynamicSharedMemorySize, SMEM_BYTES);

    // 0) pre-round tf32 inputs
    {
        int n4;
        n4 = TOK * DD / 4;
        round_tf32_kernel<<<(n4 + 255) / 256, 256>>>((const float4*)x, (float4*)xr, n4);
        n4 = HH * LDIM * FFND / 4;
        round_tf32_kernel<<<(n4 + 255) / 256, 256>>>((const float4*)W1, (float4*)w1r, n4);
        round_tf32_kernel<<<(n4 + 255) / 256, 256>>>((const float4*)W2, (float4*)w2r, n4);
        n4 = DD * DD / 4;
        round_tf32_kernel<<<(n4 + 255) / 256, 256>>>((const float4*)out_W, (float4*)owr, n4);
    }

    // 1) scale/shift
    emb_kernel<<<dim3(8, 4), 256>>>(emb, emb_W, emb_b, ss);

    // 2) h1 = round(gelu(xh @ W1 + b1)): per head M=16384, N=512, K=128
    mma_gemm<0><<<dim3(4, 128, 8), 256, SMEM_BYTES>>>(
        xr, 128, DD,
        w1r, (long)LDIM * FFND, FFND,
        h1, FFND, HH * FFND,
        b1, FFND, nullptr, LDIM);

    // 3) y = h1 @ W2 + b2: per head M=16384, N=128, K=512
    mma_gemm<1><<<dim3(1, 128, 8), 256, SMEM_BYTES>>>(
        h1, FFND, HH * FFND,
        w2r, (long)FFND * LDIM, LDIM,
        yv, LDIM, DD,
        b2, LDIM, nullptr, FFND);

    // 4) g = round(silu(modulated LN(y)))
    ln_mod_silu<<<TOK, 256>>>(yv, ss, ln_w, ln_b, gg);

    // 5) out = x + g @ out_W + out_b: M=16384, N=1024, K=1024
    mma_gemm<2><<<dim3(8, 128, 1), 256, SMEM_BYTES>>>(
        gg, 0, DD,
        owr, 0, DD,
        out, 0, DD,
        out_b, 0, x, DD);
}

// round 7
// speedup vs baseline: 3.4785x; 1.6582x over previous
#include <cuda_runtime.h>
#include <cuda_fp16.h>
#include <cstdint>
#include <math.h>

// Problem constants
#define BB   4
#define TT   4096
#define HH   8
#define LDIM 128
#define FFND 512
#define DD   1024
#define TOK  (BB*TT)
#define TED  2048

// GEMM tiling (fp16 operands)
#define BM 128
#define BN 128
#define BKC 32
#define STAGES 4
#define ASTR 40        // halves per A row (80B, 16B-aligned, conflict-free ldmatrix)
#define BSTR 136       // halves per B row (272B, 16B-aligned, conflict-free ldmatrix)
#define A_ST (BM*ASTR)         // 5120 halves / stage
#define B_ST (BKC*BSTR)        // 4352 halves / stage
#define SMEM_BYTES (STAGES*(A_ST+B_ST)*2)   // 75776 B

// Scratch
__device__ float  g_ss[BB * 2 * DD];
__device__ __half g_h1[(long)TOK * HH * FFND];
__device__ float  g_y [(long)TOK * DD];
__device__ __half g_g [(long)TOK * DD];
__device__ __half g_xh[(long)TOK * DD];
__device__ __half g_w1h[HH * LDIM * FFND];
__device__ __half g_w2h[HH * FFND * LDIM];
__device__ __half g_owh[DD * DD];

__device__ __forceinline__ float silu_f(float v) { return v / (1.0f + expf(-v)); }
__device__ __forceinline__ float gelu_f(float v) { return 0.5f * v * (1.0f + erff(v * 0.70710678118654752f)); }
__device__ __forceinline__ uint32_t h2u(__half2 h) {
    union { __half2 h; uint32_t u; } cvt;
    cvt.h = h;
    return cvt.u;
}
static __device__ __forceinline__ uint32_t smem_u32(const void* p) {
    uint32_t a;
    asm("{ .reg .u64 t; cvta.to.shared.u64 t, %1; cvt.u32.u64 %0, t; }" : "=r"(a) : "l"(p));
    return a;
}
__device__ __forceinline__ void cp_async16(uint32_t dst, const void* src) {
    asm volatile("cp.async.cg.shared.global [%0], [%1], 16;" :: "r"(dst), "l"(src));
}
#define CP_COMMIT() asm volatile("cp.async.commit_group;" ::: "memory")
#define CP_WAIT2()  asm volatile("cp.async.wait_group 2;" ::: "memory")

// ---------------------------------------------------------------------------
// f32 -> f16 conversion pre-pass
// ---------------------------------------------------------------------------
__global__ __launch_bounds__(256) void to_half_kernel(
    const float4* __restrict__ in, uint2* __restrict__ out, int n4)
{
    int i = blockIdx.x * 256 + threadIdx.x;
    if (i < n4) {
        float4 v = in[i];
        uint2 o;
        o.x = h2u(__floats2half2_rn(v.x, v.y));
        o.y = h2u(__floats2half2_rn(v.z, v.w));
        out[i] = o;
    }
}

// ---------------------------------------------------------------------------
// fp16 mma.sync m16n8k16 GEMM, cp.async 4-stage, ldmatrix fragments.
// Block 128x128, BK=32. 8 warps = 2(m) x 4(n), warp tile 64x32.
// CT: output type (EPI 0 -> __half, else float)
// EPI: 0 = bias+gelu -> half (h1), 1 = bias -> float, 2 = bias+residual -> float
// ---------------------------------------------------------------------------
template <int EPI, typename CT>
__global__ void __launch_bounds__(256, 2) mma_gemm(
    const __half* __restrict__ A, long aZ, int lda,
    const __half* __restrict__ B, long bZ, int ldb,
    CT* __restrict__ C, long cZ, int ldc,
    const float* __restrict__ bias, int biasZ,
    const float* __restrict__ extra, int K)
{
    extern __shared__ __half sm[];
    const uint32_t sA = smem_u32(sm);                       // [STAGES][BM][ASTR]
    const uint32_t sB = sA + STAGES * A_ST * 2;             // [STAGES][BKC][BSTR]

    const int tid  = threadIdx.x;
    const int lane = tid & 31, wid = tid >> 5;
    const int wm   = wid >> 2, wn = wid & 3;
    const int gid  = lane >> 2, tig = lane & 3;
    const int bx = blockIdx.x, by = blockIdx.y, bz = blockIdx.z;
    const int nC = K / BKC;

    const __half* Ap = A + aZ * bz + (long)(by * BM) * lda;
    const __half* Bp = B + bZ * bz + bx * BN;

    // cp.async mapping: A row = tid>>1, 2 chunks of 16B; B krow = tid>>3, 2 chunks
    const int ar = tid >> 1, ac0 = (tid & 1) * 2;
    const int bk = tid >> 3, bc0 = (tid & 7) * 2;

    float acc[4][4][4];
    #pragma unroll
    for (int i = 0; i < 4; i++)
        #pragma unroll
        for (int j = 0; j < 4; j++)
            #pragma unroll
            for (int e = 0; e < 4; e++) acc[i][j][e] = 0.0f;

    auto issue = [&](int c, int s) {
        const __half* a_src = Ap + (long)ar * lda + c * BKC;
        const uint32_t a_dst = sA + (uint32_t)(s * A_ST + ar * ASTR) * 2;
        #pragma unroll
        for (int p = 0; p < 2; p++)
            cp_async16(a_dst + (ac0 + p) * 16, a_src + (ac0 + p) * 8);
        const __half* b_src = Bp + (long)(c * BKC + bk) * ldb;
        const uint32_t b_dst = sB + (uint32_t)(s * B_ST + bk * BSTR) * 2;
        #pragma unroll
        for (int p = 0; p < 2; p++)
            cp_async16(b_dst + (bc0 + p) * 16, b_src + (bc0 + p) * 8);
    };

    #pragma unroll
    for (int s = 0; s < STAGES - 1; s++) {
        if (s < nC) issue(s, s);
        CP_COMMIT();
    }

    // ldmatrix per-lane base offsets
    const int a_row = wm * 64 + (lane & 15);          // + i*16
    const int a_col = (lane >> 4) << 3;               // + kb
    const int b_row = lane & 15;                      // + kb
    const int b_col = wn * 32;                        // + j*8

    for (int c = 0; c < nC; c++) {
        CP_WAIT2();
        __syncthreads();
        const int nxt = c + STAGES - 1;
        if (nxt < nC) issue(nxt, nxt & (STAGES - 1));
        CP_COMMIT();

        const uint32_t aS = sA + (uint32_t)((c & (STAGES - 1)) * A_ST) * 2;
        const uint32_t bS = sB + (uint32_t)((c & (STAGES - 1)) * B_ST) * 2;
        #pragma unroll
        for (int ks = 0; ks < 2; ks++) {
            const int kb = ks * 16;
            uint32_t af[4][4], bf[4][2];
            #pragma unroll
            for (int i = 0; i < 4; i++) {
                const uint32_t addr = aS + (uint32_t)((a_row + i * 16) * ASTR + kb + a_col) * 2;
                asm volatile("ldmatrix.sync.aligned.m8n8.x4.shared.b16 {%0,%1,%2,%3}, [%4];"
                             : "=r"(af[i][0]), "=r"(af[i][1]), "=r"(af[i][2]), "=r"(af[i][3])
                             : "r"(addr));
            }
            #pragma unroll
            for (int j = 0; j < 4; j++) {
                const uint32_t addr = bS + (uint32_t)((kb + b_row) * BSTR + b_col + j * 8) * 2;
                asm volatile("ldmatrix.sync.aligned.m8n8.x2.trans.shared.b16 {%0,%1}, [%2];"
                             : "=r"(bf[j][0]), "=r"(bf[j][1]) : "r"(addr));
            }
            #pragma unroll
            for (int i = 0; i < 4; i++)
                #pragma unroll
                for (int j = 0; j < 4; j++)
                    asm volatile(
                        "mma.sync.aligned.m16n8k16.row.col.f32.f16.f16.f32 "
                        "{%0,%1,%2,%3}, {%4,%5,%6,%7}, {%8,%9}, {%0,%1,%2,%3};"
                        : "+f"(acc[i][j][0]), "+f"(acc[i][j][1]),
                          "+f"(acc[i][j][2]), "+f"(acc[i][j][3])
                        : "r"(af[i][0]), "r"(af[i][1]), "r"(af[i][2]), "r"(af[i][3]),
                          "r"(bf[j][0]), "r"(bf[j][1]));
        }
    }

    // ---- epilogue ----
    const long zC = cZ * bz;
    const float* bsp = bias + (long)biasZ * bz;
    #pragma unroll
    for (int i = 0; i < 4; i++) {
        const int r0 = by * BM + wm * 64 + i * 16 + gid;
        #pragma unroll
        for (int j = 0; j < 4; j++) {
            const int cn = bx * BN + wn * 32 + j * 8 + tig * 2;
            const float b0 = bsp[cn], b1 = bsp[cn + 1];
            float v00 = acc[i][j][0] + b0, v01 = acc[i][j][1] + b1;
            float v10 = acc[i][j][2] + b0, v11 = acc[i][j][3] + b1;
            if (EPI == 0) {
                v00 = gelu_f(v00); v01 = gelu_f(v01);
                v10 = gelu_f(v10); v11 = gelu_f(v11);
            }
            if (EPI == 2) {
                v00 += extra[(long)r0 * ldc + cn];
                v01 += extra[(long)r0 * ldc + cn + 1];
                v10 += extra[(long)(r0 + 8) * ldc + cn];
                v11 += extra[(long)(r0 + 8) * ldc + cn + 1];
            }
            if (EPI == 0) {
                __half* Ch = (__half*)C;
                *(uint32_t*)(Ch + zC + (long)r0 * ldc + cn) =
                    h2u(__floats2half2_rn(v00, v01));
                *(uint32_t*)(Ch + zC + (long)(r0 + 8) * ldc + cn) =
                    h2u(__floats2half2_rn(v10, v11));
            } else {
                float* Cf = (float*)C;
                float2 lo = { v00, v01 }, hi = { v10, v11 };
                *(float2*)(Cf + zC + (long)r0 * ldc + cn)       = lo;
                *(float2*)(Cf + zC + (long)(r0 + 8) * ldc + cn) = hi;
            }
        }
    }
}

// ---------------------------------------------------------------------------
// emb: ss[b,:] = silu(emb[b,:]) @ emb_W + emb_b
// ---------------------------------------------------------------------------
__global__ __launch_bounds__(256) void emb_kernel(
    const float* __restrict__ emb, const float* __restrict__ embW,
    const float* __restrict__ embb, float* __restrict__ ss)
{
    __shared__ float se[TED];
    const int b = blockIdx.y;
    const int j = blockIdx.x * 256 + threadIdx.x;
    for (int i = threadIdx.x; i < TED; i += 256)
        se[i] = silu_f(emb[b * TED + i]);
    __syncthreads();
    float acc = embb[j];
    #pragma unroll 8
    for (int k = 0; k < TED; k++)
        acc += se[k] * embW[(long)k * TED + j];
    ss[b * TED + j] = acc;
}

// ---------------------------------------------------------------------------
// per-token LayerNorm -> modulate -> SiLU -> fp16 (feeds GEMM3)
// ---------------------------------------------------------------------------
__global__ __launch_bounds__(256) void ln_mod_silu(
    const float* __restrict__ y, const float* __restrict__ ss,
    const float* __restrict__ lnw, const float* __restrict__ lnb,
    __half* __restrict__ g)
{
    const long t = blockIdx.x;
    const int tid = threadIdx.x;
    const int c = tid * 4;

    float4 v = *(const float4*)(y + t * DD + c);
    float s = v.x + v.y + v.z + v.w;
    float q = v.x * v.x + v.y * v.y + v.z * v.z + v.w * v.w;
    #pragma unroll
    for (int o = 16; o; o >>= 1) {
        s += __shfl_xor_sync(0xffffffffu, s, o);
        q += __shfl_xor_sync(0xffffffffu, q, o);
    }
    __shared__ float rs[8], rq[8];
    __shared__ float smean, srstd;
    if ((tid & 31) == 0) { rs[tid >> 5] = s; rq[tid >> 5] = q; }
    __syncthreads();
    if (tid == 0) {
        float S = 0.f, Q = 0.f;
        #pragma unroll
        for (int i = 0; i < 8; i++) { S += rs[i]; Q += rq[i]; }
        float mean = S * (1.0f / DD);
        float var  = Q * (1.0f / DD) - mean * mean;
        smean = mean;
        srstd = rsqrtf(var + 1e-5f);
    }
    __syncthreads();
    const float mean = smean, rstd = srstd;

    const int b = (int)(t >> 12);
    float4 sc = *(const float4*)(ss + b * TED + c);
    float4 sh = *(const float4*)(ss + b * TED + DD + c);
    float4 w4 = *(const float4*)(lnw + c);
    float4 b4 = *(const float4*)(lnb + c);

    float o0, o1, o2, o3; float h;
    h = (v.x - mean) * rstd * w4.x + b4.x; h = h * (1.f + sc.x) + sh.x; o0 = silu_f(h);
    h = (v.y - mean) * rstd * w4.y + b4.y; h = h * (1.f + sc.y) + sh.y; o1 = silu_f(h);
    h = (v.z - mean) * rstd * w4.z + b4.z; h = h * (1.f + sc.z) + sh.z; o2 = silu_f(h);
    h = (v.w - mean) * rstd * w4.w + b4.w; h = h * (1.f + sc.w) + sh.w; o3 = silu_f(h);
    uint2 o;
    o.x = h2u(__floats2half2_rn(o0, o1));
    o.y = h2u(__floats2half2_rn(o2, o3));
    *(uint2*)(g + t * DD + c) = o;
}

// ---------------------------------------------------------------------------
extern "C" void kernel_launch(void* const* d_in, const int* in_sizes, int n_in,
                              void* d_out, int out_size)
{
    const float* x     = (const float*)d_in[0];
    const float* emb   = (const float*)d_in[1];
    const float* W1    = (const float*)d_in[2];
    const float* b1    = (const float*)d_in[3];
    const float* W2    = (const float*)d_in[4];
    const float* b2    = (const float*)d_in[5];
    const float* ln_w  = (const float*)d_in[6];
    const float* ln_b  = (const float*)d_in[7];
    const float* emb_W = (const float*)d_in[8];
    const float* emb_b = (const float*)d_in[9];
    const float* out_W = (const float*)d_in[10];
    const float* out_b = (const float*)d_in[11];
    float* out = (float*)d_out;

    float *ss, *yv;
    __half *h1, *gg, *xh, *w1h, *w2h, *owh;
    cudaGetSymbolAddress((void**)&ss, g_ss);
    cudaGetSymbolAddress((void**)&h1, g_h1);
    cudaGetSymbolAddress((void**)&yv, g_y);
    cudaGetSymbolAddress((void**)&gg, g_g);
    cudaGetSymbolAddress((void**)&xh, g_xh);
    cudaGetSymbolAddress((void**)&w1h, g_w1h);
    cudaGetSymbolAddress((void**)&w2h, g_w2h);
    cudaGetSymbolAddress((void**)&owh, g_owh);

    cudaFuncSetAttribute(reinterpret_cast<const void*>(&mma_gemm<0, __half>),
                         cudaFuncAttributeMaxDynamicSharedMemorySize, SMEM_BYTES);
    cudaFuncSetAttribute(reinterpret_cast<const void*>(&mma_gemm<1, float>),
                         cudaFuncAttributeMaxDynamicSharedMemorySize, SMEM_BYTES);
    cudaFuncSetAttribute(reinterpret_cast<const void*>(&mma_gemm<2, float>),
                         cudaFuncAttributeMaxDynamicSharedMemorySize, SMEM_BYTES);

    // 0) convert GEMM operands to fp16
    {
        int n4;
        n4 = TOK * DD / 4;
        to_half_kernel<<<(n4 + 255) / 256, 256>>>((const float4*)x, (uint2*)xh, n4);
        n4 = HH * LDIM * FFND / 4;
        to_half_kernel<<<(n4 + 255) / 256, 256>>>((const float4*)W1, (uint2*)w1h, n4);
        to_half_kernel<<<(n4 + 255) / 256, 256>>>((const float4*)W2, (uint2*)w2h, n4);
        n4 = DD * DD / 4;
        to_half_kernel<<<(n4 + 255) / 256, 256>>>((const float4*)out_W, (uint2*)owh, n4);
    }

    // 1) scale/shift
    emb_kernel<<<dim3(8, 4), 256>>>(emb, emb_W, emb_b, ss);

    // 2) h1 = half(gelu(xh @ W1 + b1)): per head M=16384, N=512, K=128
    mma_gemm<0, __half><<<dim3(4, 128, 8), 256, SMEM_BYTES>>>(
        xh, 128, DD,
        w1h, (long)LDIM * FFND, FFND,
        h1, FFND, HH * FFND,
        b1, FFND, nullptr, LDIM);

    // 3) y = h1 @ W2 + b2 (fp32 out): per head M=16384, N=128, K=512
    mma_gemm<1, float><<<dim3(1, 128, 8), 256, SMEM_BYTES>>>(
        h1, FFND, HH * FFND,
        w2h, (long)FFND * LDIM, LDIM,
        yv, LDIM, DD,
        b2, LDIM, nullptr, FFND);

    // 4) g = half(silu(modulated LN(y)))
    ln_mod_silu<<<TOK, 256>>>(yv, ss, ln_w, ln_b, gg);

    // 5) out = x + g @ out_W + out_b: M=16384, N=1024, K=1024
    mma_gemm<2, float><<<dim3(8, 128, 1), 256, SMEM_BYTES>>>(
        gg, 0, DD,
        owh, 0, DD,
        out, 0, DD,
        out_b, 0, x, DD);
}